// round 15
// baseline (speedup 1.0000x reference)
#include <cuda_runtime.h>

// Soft_NN forward == exact 1-NN: out[b,n,:] = y_c[b, argmin_m dist(x[b,n], y[b,m]), :]
// dist lane-wise = fmaf(-2, s, fl(x2+y2)); s, x2, y2 sequential fp32 FMA chains —
// bit-identical to R5/R11/R12 passing kernels (rel_err 0.0).
// R14 = R11 body (simple unrolled loop; R12 pipeline was neutral) with the 8
//       per-k pack-MOVs eliminated via a DUPLICATED-Y smem tile:
//       Yd[k][2m] = Yd[k][2m+1] = y[m][k], so LDS.128 directly yields (y,y)
//       FFMA2 operands. Mainloop/k: 6 LDS.128 + 32 FFMA2, no MOVs.

#define B_   4
#define N_   4096
#define M_   4096
#define C_   32
#define BN   128
#define BM   128
#define NTHR 256
#define NCHUNK (M_ / BM)      // 32
#define XSTR 132              // Xs row stride (floats), 16B-aligned rows
#define YDSTR 260             // dup-Y row stride (floats, 256 data + pad), 16B-aligned

typedef unsigned long long u64v;

__device__ float g_x2[B_ * N_];
__device__ float g_y2[B_ * M_];

static __device__ __forceinline__ u64v pack2(float lo, float hi) {
    u64v r;
    asm("mov.b64 %0, {%1, %2};" : "=l"(r)
        : "r"(__float_as_uint(lo)), "r"(__float_as_uint(hi)));
    return r;
}
static __device__ __forceinline__ u64v fma2(u64v a, u64v b, u64v c) {
    u64v d;
    asm("fma.rn.f32x2 %0, %1, %2, %3;" : "=l"(d) : "l"(a), "l"(b), "l"(c));
    return d;
}
static __device__ __forceinline__ u64v add2(u64v a, u64v b) {
    u64v d;
    asm("add.rn.f32x2 %0, %1, %2;" : "=l"(d) : "l"(a), "l"(b));
    return d;
}
static __device__ __forceinline__ void unpack2(u64v v, float& lo, float& hi) {
    unsigned ulo, uhi;
    asm("mov.b64 {%0, %1}, %2;" : "=r"(ulo), "=r"(uhi) : "l"(v));
    lo = __uint_as_float(ulo);
    hi = __uint_as_float(uhi);
}

// ---- pre-kernel: squared norms, sequential c-order chain (reference rounding) ----
__global__ void sq_norms_kernel(const float* __restrict__ x,
                                const float* __restrict__ y)
{
    int idx = blockIdx.x * blockDim.x + threadIdx.x;   // 0 .. 32767
    const float4* s4;
    float* dst;
    if (idx < B_ * N_) {
        s4 = (const float4*)(x + (size_t)idx * C_);
        dst = g_x2 + idx;
    } else {
        int r = idx - B_ * N_;
        s4 = (const float4*)(y + (size_t)r * C_);
        dst = g_y2 + r;
    }
    float s = 0.f;
    #pragma unroll
    for (int r = 0; r < 8; r++) {
        float4 v = s4[r];
        s = fmaf(v.x, v.x, s); s = fmaf(v.y, v.y, s);
        s = fmaf(v.z, v.z, s); s = fmaf(v.w, v.w, s);
    }
    *dst = s;
}

// smem (floats): Xs[32][XSTR] | Yd0[32][YDSTR] | Yd1[32][YDSTR]
#define SMEM_FLOATS (C_ * XSTR + 2 * C_ * YDSTR)

__global__ __launch_bounds__(NTHR, 1)
void soft_nn_kernel(const float* __restrict__ x,
                    const float* __restrict__ y,
                    const float* __restrict__ yc,
                    float* __restrict__ out)
{
    extern __shared__ __align__(16) float smem[];
    float (*Xs)[XSTR] = (float(*)[XSTR])smem;            // transposed X tile
    float* YdBase = smem + C_ * XSTR;                    // two dup-Y [C_][YDSTR] buffers

    const int tid = threadIdx.x;
    const int tx  = tid & 15;        // 16 m-lanes, 8 m each
    const int ty  = tid >> 4;        // 16 n-lanes, 8 n each
    const int blk = blockIdx.x;      // 0..127
    const int b   = blk >> 5;
    const int n0  = (blk & 31) * BN;

    const float4* xg  = (const float4*)(x + ((size_t)b * N_ + n0) * C_);
    const float4* yg  = (const float4*)(y + (size_t)b * M_ * C_);
    const float*  y2g = g_y2 + b * M_;

    // ---- prologue: chunk0 LDG first (latency), then X tile transpose ----
    float4 pf[4];
    #pragma unroll
    for (int r = 0; r < 4; r++) pf[r] = yg[tid + NTHR * r];

    #pragma unroll
    for (int t = tid; t < BN * C_ / 4; t += NTHR) {
        int n  = t >> 3;             // 8 float4 per row (C=32)
        int c4 = (t & 7) << 2;
        float4 v = xg[t];
        Xs[c4 + 0][n] = v.x;
        Xs[c4 + 1][n] = v.y;
        Xs[c4 + 2][n] = v.z;
        Xs[c4 + 3][n] = v.w;
    }

    // x2 native pairs for this thread's 8 queries (pre-kernel output, 32B aligned)
    u64v x2p[4];
    {
        const ulonglong2* p = (const ulonglong2*)(g_x2 + b * N_ + n0 + ty * 8);
        ulonglong2 a = p[0], c = p[1];
        x2p[0] = a.x; x2p[1] = a.y; x2p[2] = c.x; x2p[3] = c.y;
    }

    // store chunk0 into buffer 0, duplicated: Yd[c][2m] = Yd[c][2m+1] = y
    #pragma unroll
    for (int r = 0; r < 4; r++) {
        int t  = tid + NTHR * r;
        int m  = t >> 3;
        int c4 = (t & 7) << 2;
        float4 v = pf[r];
        *(float2*)&YdBase[(c4 + 0) * YDSTR + 2 * m] = make_float2(v.x, v.x);
        *(float2*)&YdBase[(c4 + 1) * YDSTR + 2 * m] = make_float2(v.y, v.y);
        *(float2*)&YdBase[(c4 + 2) * YDSTR + 2 * m] = make_float2(v.z, v.z);
        *(float2*)&YdBase[(c4 + 3) * YDSTR + 2 * m] = make_float2(v.w, v.w);
    }
    __syncthreads();

    const u64v NEG2 = pack2(-2.0f, -2.0f);

    float bestd[8];
    int   bestm[8];
    #pragma unroll
    for (int i = 0; i < 8; i++) { bestd[i] = 3.4e38f; bestm[i] = 0; }

    for (int ic = 0; ic < NCHUNK; ic++) {
        const int mc = ic * BM;
        const float* Yc = YdBase + (ic & 1) * (C_ * YDSTR);

        // prefetch next chunk (consumed after compute; latency hidden)
        if (ic + 1 < NCHUNK) {
            const float4* ygn = yg + ((mc + BM) * C_) / 4;
            #pragma unroll
            for (int r = 0; r < 4; r++) pf[r] = ygn[tid + NTHR * r];
        }

        // y2 for this thread's 8 candidates (L2-resident, two LDG.128)
        float4 yya = *(const float4*)(y2g + mc + tx * 4);
        float4 yyb = *(const float4*)(y2g + mc + 64 + tx * 4);
        float yyr[8] = { yya.x, yya.y, yya.z, yya.w,
                         yyb.x, yyb.y, yyb.z, yyb.w };

        // ---- mainloop: per k = 2 LDS.128 (x pairs) + 4 LDS.128 (dup-y pairs)
        //      + 32 FFMA2. No MOVs; LDS results feed FFMA2 directly.
        //      Values and FFMA2 order identical to R11 -> bit-identical dists.
        u64v acc[4][8];
        #pragma unroll
        for (int i2 = 0; i2 < 4; i2++)
            #pragma unroll
            for (int j = 0; j < 8; j++) acc[i2][j] = 0ULL;

        #pragma unroll 8
        for (int k = 0; k < C_; k++) {
            ulonglong2 xp = *(const ulonglong2*)&Xs[k][ty * 8];       // (x0,x1),(x2,x3)
            ulonglong2 xq = *(const ulonglong2*)&Xs[k][ty * 8 + 4];   // (x4,x5),(x6,x7)
            const float* yrow = Yc + k * YDSTR;
            ulonglong2 ya01 = *(const ulonglong2*)&yrow[8 * tx];            // (m0,m0),(m1,m1)
            ulonglong2 ya23 = *(const ulonglong2*)&yrow[8 * tx + 4];        // (m2,m2),(m3,m3)
            ulonglong2 yb01 = *(const ulonglong2*)&yrow[128 + 8 * tx];      // (m64+..)
            ulonglong2 yb23 = *(const ulonglong2*)&yrow[128 + 8 * tx + 4];
            u64v xpair[4] = { xp.x, xp.y, xq.x, xq.y };
            u64v yp[8] = { ya01.x, ya01.y, ya23.x, ya23.y,
                           yb01.x, yb01.y, yb23.x, yb23.y };
            #pragma unroll
            for (int i2 = 0; i2 < 4; i2++)
                #pragma unroll
                for (int j = 0; j < 8; j++)
                    acc[i2][j] = fma2(xpair[i2], yp[j], acc[i2][j]);
        }

        // ---- packed epilogue: d2 = fma2(acc, -2, add2(x2pair, y2dup)) ----
        // lane-wise identical to fmaf(-2, s, __fadd_rn(x2, y2)).
        #pragma unroll
        for (int j = 0; j < 8; j++) {
            int  m   = mc + ((j < 4) ? (tx * 4 + j) : (64 + tx * 4 + (j - 4)));
            u64v y2d = pack2(yyr[j], yyr[j]);
            #pragma unroll
            for (int i2 = 0; i2 < 4; i2++) {
                u64v d2 = fma2(acc[i2][j], NEG2, add2(x2p[i2], y2d));
                float dlo, dhi;
                unpack2(d2, dlo, dhi);
                // per n-slot, m ascends across j and chunks: strict < keeps earliest m
                if (dlo < bestd[2 * i2])     { bestd[2 * i2]     = dlo; bestm[2 * i2]     = m; }
                if (dhi < bestd[2 * i2 + 1]) { bestd[2 * i2 + 1] = dhi; bestm[2 * i2 + 1] = m; }
            }
        }

        // ---- store next chunk (duplicated) into the other buffer ----
        if (ic + 1 < NCHUNK) {
            float* Yn = YdBase + ((ic + 1) & 1) * (C_ * YDSTR);
            #pragma unroll
            for (int r = 0; r < 4; r++) {
                int t  = tid + NTHR * r;
                int m  = t >> 3;
                int c4 = (t & 7) << 2;
                float4 v = pf[r];
                *(float2*)&Yn[(c4 + 0) * YDSTR + 2 * m] = make_float2(v.x, v.x);
                *(float2*)&Yn[(c4 + 1) * YDSTR + 2 * m] = make_float2(v.y, v.y);
                *(float2*)&Yn[(c4 + 2) * YDSTR + 2 * m] = make_float2(v.z, v.z);
                *(float2*)&Yn[(c4 + 3) * YDSTR + 2 * m] = make_float2(v.w, v.w);
            }
        }
        __syncthreads();   // single barrier per chunk
    }

    // ---- cross-tx reduction (reuse smem as scratch) ----
    float* redD = smem;                    // BN*16 = 2048 floats
    int*   redM = (int*)(smem + BN * 16);  // 2048 ints
    #pragma unroll
    for (int i = 0; i < 8; i++) {
        int n = ty * 8 + i;
        redD[n * 16 + tx] = bestd[i];
        redM[n * 16 + tx] = bestm[i];
    }
    __syncthreads();
    if (tid < BN) {
        float bd = redD[tid * 16];
        int   bm = redM[tid * 16];
        #pragma unroll
        for (int t = 1; t < 16; t++) {
            float d = redD[tid * 16 + t];
            int   m = redM[tid * 16 + t];
            if (d < bd || (d == bd && m < bm)) { bd = d; bm = m; }
        }
        const float* src = yc + ((size_t)b * M_ + bm) * 3;
        float*       dst = out + ((size_t)b * N_ + n0 + tid) * 3;
        dst[0] = src[0];
        dst[1] = src[1];
        dst[2] = src[2];
    }
}

extern "C" void kernel_launch(void* const* d_in, const int* in_sizes, int n_in,
                              void* d_out, int out_size)
{
    const float* x  = (const float*)d_in[0];   // x_f  [4,4096,32]
    const float* y  = (const float*)d_in[1];   // y_f  [4,4096,32]
    const float* yc = (const float*)d_in[2];   // y_c  [4,4096,3]
    // d_in[3] = temp_inv (positive constant; does not affect argmax)
    float* out = (float*)d_out;                // [4,4096,3]

    sq_norms_kernel<<<(B_ * (N_ + M_)) / 256, 256>>>(x, y);

    const int smem_bytes = SMEM_FLOATS * (int)sizeof(float);  // ~83.5KB
    cudaFuncSetAttribute(soft_nn_kernel,
                         cudaFuncAttributeMaxDynamicSharedMemorySize, smem_bytes);
    soft_nn_kernel<<<(B_ * N_) / BN, NTHR, smem_bytes>>>(x, y, yc, out);
}

// round 16
// speedup vs baseline: 1.4334x; 1.4334x over previous
#include <cuda_runtime.h>

// Soft_NN forward == exact 1-NN: out[b,n,:] = y_c[b, argmin_m dist(x[b,n], y[b,m]), :]
// dist lane-wise = fmaf(-2, s, fl(x2+y2)); s, x2, y2 sequential fp32 FMA chains —
// bit-identical to R5/R11/R12 passing kernels (rel_err 0.0).
// R15 = R11 frame + zero-MOV mainloop with CONFLICT-FREE duplicated-Y layout:
//   pair for chunk-index m stored at  h*128 + (j/2)*64 + (m%64/4)*4 + (j%2)*2
//   (h=m/64, j=m%4), so each thread's four 16B y-reads are lane-consecutive.
//   R14's 8*tx-stride layout was 4-way bank-conflicted (L1=73%, 188us).

#define B_   4
#define N_   4096
#define M_   4096
#define C_   32
#define BN   128
#define BM   128
#define NTHR 256
#define NCHUNK (M_ / BM)      // 32
#define XSTR 132              // Xs row stride (floats), 16B-aligned rows
#define YDSTR 260             // dup-Y row stride (floats, 256 data + pad)

typedef unsigned long long u64v;

__device__ float g_x2[B_ * N_];
__device__ float g_y2[B_ * M_];

static __device__ __forceinline__ u64v pack2(float lo, float hi) {
    u64v r;
    asm("mov.b64 %0, {%1, %2};" : "=l"(r)
        : "r"(__float_as_uint(lo)), "r"(__float_as_uint(hi)));
    return r;
}
static __device__ __forceinline__ u64v fma2(u64v a, u64v b, u64v c) {
    u64v d;
    asm("fma.rn.f32x2 %0, %1, %2, %3;" : "=l"(d) : "l"(a), "l"(b), "l"(c));
    return d;
}
static __device__ __forceinline__ u64v add2(u64v a, u64v b) {
    u64v d;
    asm("add.rn.f32x2 %0, %1, %2;" : "=l"(d) : "l"(a), "l"(b));
    return d;
}
static __device__ __forceinline__ void unpack2(u64v v, float& lo, float& hi) {
    unsigned ulo, uhi;
    asm("mov.b64 {%0, %1}, %2;" : "=r"(ulo), "=r"(uhi) : "l"(v));
    lo = __uint_as_float(ulo);
    hi = __uint_as_float(uhi);
}

// ---- pre-kernel: squared norms, sequential c-order chain (reference rounding) ----
__global__ void sq_norms_kernel(const float* __restrict__ x,
                                const float* __restrict__ y)
{
    int idx = blockIdx.x * blockDim.x + threadIdx.x;   // 0 .. 32767
    const float4* s4;
    float* dst;
    if (idx < B_ * N_) {
        s4 = (const float4*)(x + (size_t)idx * C_);
        dst = g_x2 + idx;
    } else {
        int r = idx - B_ * N_;
        s4 = (const float4*)(y + (size_t)r * C_);
        dst = g_y2 + r;
    }
    float s = 0.f;
    #pragma unroll
    for (int r = 0; r < 8; r++) {
        float4 v = s4[r];
        s = fmaf(v.x, v.x, s); s = fmaf(v.y, v.y, s);
        s = fmaf(v.z, v.z, s); s = fmaf(v.w, v.w, s);
    }
    *dst = s;
}

// smem (floats): Xs[32][XSTR] | Yd0[32][YDSTR] | Yd1[32][YDSTR]
#define SMEM_FLOATS (C_ * XSTR + 2 * C_ * YDSTR)

// dup-pair offset within a Yd row for chunk m-index mm (0..127)
static __device__ __forceinline__ int ydup_off(int mm) {
    int h    = mm >> 6;          // 0/1
    int r6   = mm & 63;
    int lane = r6 >> 2;          // target tx
    int j    = r6 & 3;
    return h * 128 + (j >> 1) * 64 + lane * 4 + (j & 1) * 2;
}

__global__ __launch_bounds__(NTHR, 1)
void soft_nn_kernel(const float* __restrict__ x,
                    const float* __restrict__ y,
                    const float* __restrict__ yc,
                    float* __restrict__ out)
{
    extern __shared__ __align__(16) float smem[];
    float (*Xs)[XSTR] = (float(*)[XSTR])smem;            // transposed X tile
    float* YdBase = smem + C_ * XSTR;                    // two dup-Y [C_][YDSTR] buffers

    const int tid = threadIdx.x;
    const int tx  = tid & 15;        // 16 m-lanes, 8 m each
    const int ty  = tid >> 4;        // 16 n-lanes, 8 n each
    const int blk = blockIdx.x;      // 0..127
    const int b   = blk >> 5;
    const int n0  = (blk & 31) * BN;

    const float4* xg  = (const float4*)(x + ((size_t)b * N_ + n0) * C_);
    const float4* yg  = (const float4*)(y + (size_t)b * M_ * C_);
    const float*  y2g = g_y2 + b * M_;

    // ---- prologue: chunk0 LDG first (latency), then X tile transpose ----
    float4 pf[4];
    #pragma unroll
    for (int r = 0; r < 4; r++) pf[r] = yg[tid + NTHR * r];

    #pragma unroll
    for (int t = tid; t < BN * C_ / 4; t += NTHR) {
        int n  = t >> 3;             // 8 float4 per row (C=32)
        int c4 = (t & 7) << 2;
        float4 v = xg[t];
        Xs[c4 + 0][n] = v.x;
        Xs[c4 + 1][n] = v.y;
        Xs[c4 + 2][n] = v.z;
        Xs[c4 + 3][n] = v.w;
    }

    // x2 native pairs for this thread's 8 queries (pre-kernel output, 32B aligned)
    u64v x2p[4];
    {
        const ulonglong2* p = (const ulonglong2*)(g_x2 + b * N_ + n0 + ty * 8);
        ulonglong2 a = p[0], c = p[1];
        x2p[0] = a.x; x2p[1] = a.y; x2p[2] = c.x; x2p[3] = c.y;
    }

    // store chunk0 into buffer 0, duplicated + regrouped (conflict-free reads)
    {
        #pragma unroll
        for (int r = 0; r < 4; r++) {
            int t   = tid + NTHR * r;
            int m   = t >> 3;
            int c4  = (t & 7) << 2;
            int off = ydup_off(m);
            float4 v = pf[r];
            *(float2*)&YdBase[(c4 + 0) * YDSTR + off] = make_float2(v.x, v.x);
            *(float2*)&YdBase[(c4 + 1) * YDSTR + off] = make_float2(v.y, v.y);
            *(float2*)&YdBase[(c4 + 2) * YDSTR + off] = make_float2(v.z, v.z);
            *(float2*)&YdBase[(c4 + 3) * YDSTR + off] = make_float2(v.w, v.w);
        }
    }
    __syncthreads();

    const u64v NEG2 = pack2(-2.0f, -2.0f);

    float bestd[8];
    int   bestm[8];
    #pragma unroll
    for (int i = 0; i < 8; i++) { bestd[i] = 3.4e38f; bestm[i] = 0; }

    for (int ic = 0; ic < NCHUNK; ic++) {
        const int mc = ic * BM;
        const float* Yc = YdBase + (ic & 1) * (C_ * YDSTR);

        // prefetch next chunk (consumed after compute; latency hidden)
        if (ic + 1 < NCHUNK) {
            const float4* ygn = yg + ((mc + BM) * C_) / 4;
            #pragma unroll
            for (int r = 0; r < 4; r++) pf[r] = ygn[tid + NTHR * r];
        }

        // y2 for this thread's 8 candidates (L2-resident, two LDG.128)
        float4 yya = *(const float4*)(y2g + mc + tx * 4);
        float4 yyb = *(const float4*)(y2g + mc + 64 + tx * 4);
        float yyr[8] = { yya.x, yya.y, yya.z, yya.w,
                         yyb.x, yyb.y, yyb.z, yyb.w };

        // ---- mainloop: per k = 2 LDS.128 (x, broadcast) + 4 LDS.128 (dup-y,
        //      lane-consecutive = conflict-free) + 32 FFMA2. No MOVs.
        //      Values and FFMA2 order identical to R11 -> bit-identical dists.
        u64v acc[4][8];
        #pragma unroll
        for (int i2 = 0; i2 < 4; i2++)
            #pragma unroll
            for (int j = 0; j < 8; j++) acc[i2][j] = 0ULL;

        #pragma unroll 8
        for (int k = 0; k < C_; k++) {
            ulonglong2 xp = *(const ulonglong2*)&Xs[k][ty * 8];       // (x0,x1),(x2,x3)
            ulonglong2 xq = *(const ulonglong2*)&Xs[k][ty * 8 + 4];   // (x4,x5),(x6,x7)
            const float* yrow = Yc + k * YDSTR;
            ulonglong2 ya01 = *(const ulonglong2*)&yrow[tx * 4];          // (m0,m0),(m1,m1)
            ulonglong2 ya23 = *(const ulonglong2*)&yrow[64 + tx * 4];     // (m2,m2),(m3,m3)
            ulonglong2 yb01 = *(const ulonglong2*)&yrow[128 + tx * 4];    // m+64 pairs
            ulonglong2 yb23 = *(const ulonglong2*)&yrow[192 + tx * 4];
            u64v xpair[4] = { xp.x, xp.y, xq.x, xq.y };
            u64v yp[8] = { ya01.x, ya01.y, ya23.x, ya23.y,
                           yb01.x, yb01.y, yb23.x, yb23.y };
            #pragma unroll
            for (int i2 = 0; i2 < 4; i2++)
                #pragma unroll
                for (int j = 0; j < 8; j++)
                    acc[i2][j] = fma2(xpair[i2], yp[j], acc[i2][j]);
        }

        // ---- packed epilogue: d2 = fma2(acc, -2, add2(x2pair, y2dup)) ----
        // lane-wise identical to fmaf(-2, s, __fadd_rn(x2, y2)).
        #pragma unroll
        for (int j = 0; j < 8; j++) {
            int  m   = mc + ((j < 4) ? (tx * 4 + j) : (64 + tx * 4 + (j - 4)));
            u64v y2d = pack2(yyr[j], yyr[j]);
            #pragma unroll
            for (int i2 = 0; i2 < 4; i2++) {
                u64v d2 = fma2(acc[i2][j], NEG2, add2(x2p[i2], y2d));
                float dlo, dhi;
                unpack2(d2, dlo, dhi);
                // per n-slot, m ascends across j and chunks: strict < keeps earliest m
                if (dlo < bestd[2 * i2])     { bestd[2 * i2]     = dlo; bestm[2 * i2]     = m; }
                if (dhi < bestd[2 * i2 + 1]) { bestd[2 * i2 + 1] = dhi; bestm[2 * i2 + 1] = m; }
            }
        }

        // ---- store next chunk (duplicated + regrouped) into the other buffer ----
        if (ic + 1 < NCHUNK) {
            float* Yn = YdBase + ((ic + 1) & 1) * (C_ * YDSTR);
            #pragma unroll
            for (int r = 0; r < 4; r++) {
                int t   = tid + NTHR * r;
                int m   = t >> 3;
                int c4  = (t & 7) << 2;
                int off = ydup_off(m);
                float4 v = pf[r];
                *(float2*)&Yn[(c4 + 0) * YDSTR + off] = make_float2(v.x, v.x);
                *(float2*)&Yn[(c4 + 1) * YDSTR + off] = make_float2(v.y, v.y);
                *(float2*)&Yn[(c4 + 2) * YDSTR + off] = make_float2(v.z, v.z);
                *(float2*)&Yn[(c4 + 3) * YDSTR + off] = make_float2(v.w, v.w);
            }
        }
        __syncthreads();   // single barrier per chunk
    }

    // ---- cross-tx reduction (reuse smem as scratch) ----
    float* redD = smem;                    // BN*16 = 2048 floats
    int*   redM = (int*)(smem + BN * 16);  // 2048 ints
    #pragma unroll
    for (int i = 0; i < 8; i++) {
        int n = ty * 8 + i;
        redD[n * 16 + tx] = bestd[i];
        redM[n * 16 + tx] = bestm[i];
    }
    __syncthreads();
    if (tid < BN) {
        float bd = redD[tid * 16];
        int   bm = redM[tid * 16];
        #pragma unroll
        for (int t = 1; t < 16; t++) {
            float d = redD[tid * 16 + t];
            int   m = redM[tid * 16 + t];
            if (d < bd || (d == bd && m < bm)) { bd = d; bm = m; }
        }
        const float* src = yc + ((size_t)b * M_ + bm) * 3;
        float*       dst = out + ((size_t)b * N_ + n0 + tid) * 3;
        dst[0] = src[0];
        dst[1] = src[1];
        dst[2] = src[2];
    }
}

extern "C" void kernel_launch(void* const* d_in, const int* in_sizes, int n_in,
                              void* d_out, int out_size)
{
    const float* x  = (const float*)d_in[0];   // x_f  [4,4096,32]
    const float* y  = (const float*)d_in[1];   // y_f  [4,4096,32]
    const float* yc = (const float*)d_in[2];   // y_c  [4,4096,3]
    // d_in[3] = temp_inv (positive constant; does not affect argmax)
    float* out = (float*)d_out;                // [4,4096,3]

    sq_norms_kernel<<<(B_ * (N_ + M_)) / 256, 256>>>(x, y);

    const int smem_bytes = SMEM_FLOATS * (int)sizeof(float);  // ~83.5KB
    cudaFuncSetAttribute(soft_nn_kernel,
                         cudaFuncAttributeMaxDynamicSharedMemorySize, smem_bytes);
    soft_nn_kernel<<<(B_ * N_) / BN, NTHR, smem_bytes>>>(x, y, yc, out);
}

// round 17
// speedup vs baseline: 1.9530x; 1.3626x over previous
#include <cuda_runtime.h>

// Soft_NN forward == exact 1-NN: out[b,n,:] = y_c[b, argmin_m dist(x[b,n], y[b,m]), :]
// dist lane-wise = fmaf(-2, s, fl(x2+y2)); s, x2, y2 sequential fp32 FMA chains —
// bit-identical to R5/R11/R12 passing kernels (rel_err 0.0).
// R16 = R11 champion mainloop VERBATIM (dup-Y family dead: extra LDS bytes cost
//       more than the pack-MOVs they remove). Scaffolding only:
//       - quad-buffered Ys, stores issued 2 chunks ahead
//       - __syncthreads every 2nd chunk (33 -> 17 barriers; WAR/RAW audited)
//       - next-chunk STS before epilogue so BAR's STS-drain overlaps compute

#define B_   4
#define N_   4096
#define M_   4096
#define C_   32
#define BN   128
#define BM   128
#define NTHR 256
#define NCHUNK (M_ / BM)      // 32
#define SSTR 132              // smem row stride (floats), 16B-aligned rows

typedef unsigned long long u64v;

__device__ float g_x2[B_ * N_];
__device__ float g_y2[B_ * M_];

static __device__ __forceinline__ u64v pack2(float lo, float hi) {
    u64v r;
    asm("mov.b64 %0, {%1, %2};" : "=l"(r)
        : "r"(__float_as_uint(lo)), "r"(__float_as_uint(hi)));
    return r;
}
static __device__ __forceinline__ u64v fma2(u64v a, u64v b, u64v c) {
    u64v d;
    asm("fma.rn.f32x2 %0, %1, %2, %3;" : "=l"(d) : "l"(a), "l"(b), "l"(c));
    return d;
}
static __device__ __forceinline__ u64v add2(u64v a, u64v b) {
    u64v d;
    asm("add.rn.f32x2 %0, %1, %2;" : "=l"(d) : "l"(a), "l"(b));
    return d;
}
static __device__ __forceinline__ void unpack2(u64v v, float& lo, float& hi) {
    unsigned ulo, uhi;
    asm("mov.b64 {%0, %1}, %2;" : "=r"(ulo), "=r"(uhi) : "l"(v));
    lo = __uint_as_float(ulo);
    hi = __uint_as_float(uhi);
}

// ---- pre-kernel: squared norms, sequential c-order chain (reference rounding) ----
__global__ void sq_norms_kernel(const float* __restrict__ x,
                                const float* __restrict__ y)
{
    int idx = blockIdx.x * blockDim.x + threadIdx.x;   // 0 .. 32767
    const float4* s4;
    float* dst;
    if (idx < B_ * N_) {
        s4 = (const float4*)(x + (size_t)idx * C_);
        dst = g_x2 + idx;
    } else {
        int r = idx - B_ * N_;
        s4 = (const float4*)(y + (size_t)r * C_);
        dst = g_y2 + r;
    }
    float s = 0.f;
    #pragma unroll
    for (int r = 0; r < 8; r++) {
        float4 v = s4[r];
        s = fmaf(v.x, v.x, s); s = fmaf(v.y, v.y, s);
        s = fmaf(v.z, v.z, s); s = fmaf(v.w, v.w, s);
    }
    *dst = s;
}

// smem (floats): Xs[32][SSTR] | Ys[4][32][SSTR]
#define SMEM_FLOATS (5 * C_ * SSTR)

__global__ __launch_bounds__(NTHR, 1)
void soft_nn_kernel(const float* __restrict__ x,
                    const float* __restrict__ y,
                    const float* __restrict__ yc,
                    float* __restrict__ out)
{
    extern __shared__ __align__(16) float smem[];
    float (*Xs)[SSTR] = (float(*)[SSTR])smem;            // transposed X tile
    float* YsBase = smem + C_ * SSTR;                    // four [C_][SSTR] buffers

    const int tid = threadIdx.x;
    const int tx  = tid & 15;        // 16 m-lanes, 8 m each
    const int ty  = tid >> 4;        // 16 n-lanes, 8 n each
    const int blk = blockIdx.x;      // 0..127
    const int b   = blk >> 5;
    const int n0  = (blk & 31) * BN;

    const float4* xg  = (const float4*)(x + ((size_t)b * N_ + n0) * C_);
    const float4* yg  = (const float4*)(y + (size_t)b * M_ * C_);
    const float*  y2g = g_y2 + b * M_;

    // ---- prologue: load chunk0 + chunk1, transpose X, fill buffers 0/1 ----
    float4 pf[4];
    #pragma unroll
    for (int r = 0; r < 4; r++) pf[r] = yg[tid + NTHR * r];

    #pragma unroll
    for (int t = tid; t < BN * C_ / 4; t += NTHR) {
        int n  = t >> 3;             // 8 float4 per row (C=32)
        int c4 = (t & 7) << 2;
        float4 v = xg[t];
        Xs[c4 + 0][n] = v.x;
        Xs[c4 + 1][n] = v.y;
        Xs[c4 + 2][n] = v.z;
        Xs[c4 + 3][n] = v.w;
    }

    // x2 native pairs for this thread's 8 queries (pre-kernel output, 32B aligned)
    u64v x2p[4];
    {
        const ulonglong2* p = (const ulonglong2*)(g_x2 + b * N_ + n0 + ty * 8);
        ulonglong2 a = p[0], c = p[1];
        x2p[0] = a.x; x2p[1] = a.y; x2p[2] = c.x; x2p[3] = c.y;
    }

    // store chunk0 -> buf0, then load+store chunk1 -> buf1
    #pragma unroll
    for (int r = 0; r < 4; r++) {
        int t  = tid + NTHR * r;
        int m  = t >> 3;
        int c4 = (t & 7) << 2;
        float4 v = pf[r];
        YsBase[(c4 + 0) * SSTR + m] = v.x;
        YsBase[(c4 + 1) * SSTR + m] = v.y;
        YsBase[(c4 + 2) * SSTR + m] = v.z;
        YsBase[(c4 + 3) * SSTR + m] = v.w;
    }
    {
        const float4* yg1 = yg + (BM * C_) / 4;
        #pragma unroll
        for (int r = 0; r < 4; r++) pf[r] = yg1[tid + NTHR * r];
        float* Y1 = YsBase + 1 * (C_ * SSTR);
        #pragma unroll
        for (int r = 0; r < 4; r++) {
            int t  = tid + NTHR * r;
            int m  = t >> 3;
            int c4 = (t & 7) << 2;
            float4 v = pf[r];
            Y1[(c4 + 0) * SSTR + m] = v.x;
            Y1[(c4 + 1) * SSTR + m] = v.y;
            Y1[(c4 + 2) * SSTR + m] = v.z;
            Y1[(c4 + 3) * SSTR + m] = v.w;
        }
    }
    __syncthreads();

    const u64v NEG2 = pack2(-2.0f, -2.0f);

    float bestd[8];
    int   bestm[8];
    #pragma unroll
    for (int i = 0; i < 8; i++) { bestd[i] = 3.4e38f; bestm[i] = 0; }

    for (int ic = 0; ic < NCHUNK; ic++) {
        const int mc = ic * BM;
        const float* Yc = YsBase + (ic & 3) * (C_ * SSTR);

        // prefetch chunk ic+2 (stored after the mainloop below)
        if (ic < NCHUNK - 2) {
            const float4* ygn = yg + ((mc + 2 * BM) * C_) / 4;
            #pragma unroll
            for (int r = 0; r < 4; r++) pf[r] = ygn[tid + NTHR * r];
        }

        // y2 for this thread's 8 candidates (L2-resident, two LDG.128)
        float4 yya = *(const float4*)(y2g + mc + tx * 4);
        float4 yyb = *(const float4*)(y2g + mc + 64 + tx * 4);
        float yyr[8] = { yya.x, yya.y, yya.z, yya.w,
                         yyb.x, yyb.y, yyb.z, yyb.w };

        // ---- R11 champion mainloop (verbatim): 4 LDS.128 + 8 packs + 32 FFMA2 / k ----
        u64v acc[4][8];
        #pragma unroll
        for (int i2 = 0; i2 < 4; i2++)
            #pragma unroll
            for (int j = 0; j < 8; j++) acc[i2][j] = 0ULL;

        #pragma unroll 8
        for (int k = 0; k < C_; k++) {
            ulonglong2 xp = *(const ulonglong2*)&Xs[k][ty * 8];       // (x0,x1),(x2,x3)
            ulonglong2 xq = *(const ulonglong2*)&Xs[k][ty * 8 + 4];   // (x4,x5),(x6,x7)
            float4 ya = *(const float4*)&Yc[k * SSTR + tx * 4];       // conflict-free
            float4 yb = *(const float4*)&Yc[k * SSTR + 64 + tx * 4];  // conflict-free
            u64v xpair[4] = { xp.x, xp.y, xq.x, xq.y };
            u64v yp[8] = {
                pack2(ya.x, ya.x), pack2(ya.y, ya.y), pack2(ya.z, ya.z), pack2(ya.w, ya.w),
                pack2(yb.x, yb.x), pack2(yb.y, yb.y), pack2(yb.z, yb.z), pack2(yb.w, yb.w)
            };
            #pragma unroll
            for (int i2 = 0; i2 < 4; i2++)
                #pragma unroll
                for (int j = 0; j < 8; j++)
                    acc[i2][j] = fma2(xpair[i2], yp[j], acc[i2][j]);
        }

        // ---- store chunk ic+2 BEFORE the epilogue: the BAR below drains STS,
        //      so the epilogue's ~300 cycles hide the drain ----
        if (ic < NCHUNK - 2) {
            float* Yn = YsBase + ((ic + 2) & 3) * (C_ * SSTR);
            #pragma unroll
            for (int r = 0; r < 4; r++) {
                int t  = tid + NTHR * r;
                int m  = t >> 3;
                int c4 = (t & 7) << 2;
                float4 v = pf[r];
                Yn[(c4 + 0) * SSTR + m] = v.x;
                Yn[(c4 + 1) * SSTR + m] = v.y;
                Yn[(c4 + 2) * SSTR + m] = v.z;
                Yn[(c4 + 3) * SSTR + m] = v.w;
            }
        }

        // ---- packed epilogue: d2 = fma2(acc, -2, add2(x2pair, y2dup)) ----
        // lane-wise identical to fmaf(-2, s, __fadd_rn(x2, y2)).
        #pragma unroll
        for (int j = 0; j < 8; j++) {
            int  m   = mc + ((j < 4) ? (tx * 4 + j) : (64 + tx * 4 + (j - 4)));
            u64v y2d = pack2(yyr[j], yyr[j]);
            #pragma unroll
            for (int i2 = 0; i2 < 4; i2++) {
                u64v d2 = fma2(acc[i2][j], NEG2, add2(x2p[i2], y2d));
                float dlo, dhi;
                unpack2(d2, dlo, dhi);
                // per n-slot, m ascends across j and chunks: strict < keeps earliest m
                if (dlo < bestd[2 * i2])     { bestd[2 * i2]     = dlo; bestm[2 * i2]     = m; }
                if (dhi < bestd[2 * i2 + 1]) { bestd[2 * i2 + 1] = dhi; bestm[2 * i2 + 1] = m; }
            }
        }

        // ---- barrier every 2nd chunk (quad buffer + 2-ahead stores make this
        //      sufficient: WAR read@ic-2 vs store@ic and RAW store@ic vs
        //      read@ic+2 are each separated by an odd-chunk barrier) ----
        if (ic & 1) __syncthreads();
    }

    // ---- cross-tx reduction (reuse smem as scratch; barrier at ic=31 above) ----
    float* redD = smem;                    // BN*16 = 2048 floats
    int*   redM = (int*)(smem + BN * 16);  // 2048 ints
    #pragma unroll
    for (int i = 0; i < 8; i++) {
        int n = ty * 8 + i;
        redD[n * 16 + tx] = bestd[i];
        redM[n * 16 + tx] = bestm[i];
    }
    __syncthreads();
    if (tid < BN) {
        float bd = redD[tid * 16];
        int   bm = redM[tid * 16];
        #pragma unroll
        for (int t = 1; t < 16; t++) {
            float d = redD[tid * 16 + t];
            int   m = redM[tid * 16 + t];
            if (d < bd || (d == bd && m < bm)) { bd = d; bm = m; }
        }
        const float* src = yc + ((size_t)b * M_ + bm) * 3;
        float*       dst = out + ((size_t)b * N_ + n0 + tid) * 3;
        dst[0] = src[0];
        dst[1] = src[1];
        dst[2] = src[2];
    }
}

extern "C" void kernel_launch(void* const* d_in, const int* in_sizes, int n_in,
                              void* d_out, int out_size)
{
    const float* x  = (const float*)d_in[0];   // x_f  [4,4096,32]
    const float* y  = (const float*)d_in[1];   // y_f  [4,4096,32]
    const float* yc = (const float*)d_in[2];   // y_c  [4,4096,3]
    // d_in[3] = temp_inv (positive constant; does not affect argmax)
    float* out = (float*)d_out;                // [4,4096,3]

    sq_norms_kernel<<<(B_ * (N_ + M_)) / 256, 256>>>(x, y);

    const int smem_bytes = SMEM_FLOATS * (int)sizeof(float);  // ~84.5KB
    cudaFuncSetAttribute(soft_nn_kernel,
                         cudaFuncAttributeMaxDynamicSharedMemorySize, smem_bytes);
    soft_nn_kernel<<<(B_ * N_) / BN, NTHR, smem_bytes>>>(x, y, yc, out);
}